// round 10
// baseline (speedup 1.0000x reference)
#include <cuda_runtime.h>
#include <cuda_bf16.h>
#include <math.h>
#include <stdint.h>

#define Bv 128
#define Tv 256
#define Hv 1024
#define GRID 128
#define NTHR 256

// ---------------- scratch -----------------------------------------------------
__device__ __nv_bfloat16 g_xh[(size_t)Bv * Tv * Hv];
__device__ __nv_bfloat16 g_xl[(size_t)Bv * Tv * Hv];
__device__ __nv_bfloat16 g_Wth[4][(size_t)Hv * Hv];   // [n][k] hi: 0:Wh0 1:Wi1 2:Wh1 3:Wi0
__device__ __nv_bfloat16 g_Wtl[4][(size_t)Hv * Hv];   // [n][k] lo
__device__ __nv_bfloat16 g_h0h[2][Bv * Hv], g_h0l[2][Bv * Hv];
__device__ __nv_bfloat16 g_h1h[2][Bv * Hv], g_h1l[2][Bv * Hv];
__device__ float g_bsum[2 * Hv];
__device__ float g_P[64 * 4096];          // pair partial tiles (64x64 fp32 each)
__device__ unsigned g_flag[64];           // pair release flags
__device__ unsigned g_arrive, g_gen;

// ---------------- smem layout (dynamic) -----------------------------------------
#define OFF_WRES  0
#define OFF_AH(b) (131072 + (b) * 24576)
#define OFF_AL(b) (131072 + (b) * 24576 + 8192)
#define OFF_WL(b) (131072 + (b) * 24576 + 16384)
#define OFF_CMB   131072
#define SMEM_SZ   180224

// ---------------- PTX helpers ---------------------------------------------------
__device__ __forceinline__ uint32_t smem_u32(const void* p) {
    uint32_t a;
    asm("{ .reg .u64 t; cvta.to.shared.u64 t, %1; cvt.u32.u64 %0, t; }" : "=r"(a) : "l"(p));
    return a;
}
__device__ __forceinline__ uint32_t swz(uint32_t o) { return o ^ ((o >> 3) & 0x70); }
__device__ __forceinline__ void cp16(uint32_t s, const void* g) {
    asm volatile("cp.async.cg.shared.global [%0], [%1], 16;" :: "r"(s), "l"(g));
}
__device__ __forceinline__ void ldm4(uint32_t* r, uint32_t addr) {
    asm volatile("ldmatrix.sync.aligned.m8n8.x4.shared.b16 {%0,%1,%2,%3}, [%4];"
        : "=r"(r[0]), "=r"(r[1]), "=r"(r[2]), "=r"(r[3]) : "r"(addr));
}
__device__ __forceinline__ void mma16816(float* c, const uint32_t* a, const uint32_t* b) {
    asm volatile("mma.sync.aligned.m16n8k16.row.col.f32.bf16.bf16.f32 "
        "{%0,%1,%2,%3}, {%4,%5,%6,%7}, {%8,%9}, {%0,%1,%2,%3};"
        : "+f"(c[0]), "+f"(c[1]), "+f"(c[2]), "+f"(c[3])
        : "r"(a[0]), "r"(a[1]), "r"(a[2]), "r"(a[3]), "r"(b[0]), "r"(b[1]));
}

// ---------------- grid barrier (busy-wait, no nanosleep) ---------------------------
__device__ __forceinline__ void gbar(unsigned expect) {
    __threadfence();
    __syncthreads();
    if (threadIdx.x == 0) {
        unsigned a = atomicAdd(&g_arrive, 1u);
        if (a == GRID - 1) {
            atomicExch(&g_arrive, 0u);
            __threadfence();
            atomicAdd(&g_gen, 1u);
        } else {
            while (*(volatile unsigned*)&g_gen < expect) {}
        }
        __threadfence();
    }
    __syncthreads();
}

// ---------------- bf16 split helpers ------------------------------------------------
__device__ __forceinline__ void split4(float4 v, uint2& uh, uint2& ul) {
    __nv_bfloat16 h0 = __float2bfloat16_rn(v.x), h1 = __float2bfloat16_rn(v.y);
    __nv_bfloat16 h2 = __float2bfloat16_rn(v.z), h3 = __float2bfloat16_rn(v.w);
    __nv_bfloat16 l0 = __float2bfloat16_rn(v.x - __bfloat162float(h0));
    __nv_bfloat16 l1 = __float2bfloat16_rn(v.y - __bfloat162float(h1));
    __nv_bfloat16 l2 = __float2bfloat16_rn(v.z - __bfloat162float(h2));
    __nv_bfloat16 l3 = __float2bfloat16_rn(v.w - __bfloat162float(h3));
    uh.x = (uint32_t)__bfloat16_as_ushort(h0) | ((uint32_t)__bfloat16_as_ushort(h1) << 16);
    uh.y = (uint32_t)__bfloat16_as_ushort(h2) | ((uint32_t)__bfloat16_as_ushort(h3) << 16);
    ul.x = (uint32_t)__bfloat16_as_ushort(l0) | ((uint32_t)__bfloat16_as_ushort(l1) << 16);
    ul.y = (uint32_t)__bfloat16_as_ushort(l2) | ((uint32_t)__bfloat16_as_ushort(l3) << 16);
}
__device__ __forceinline__ void split2(float a, float b, uint32_t& uh, uint32_t& ul) {
    __nv_bfloat16 h0 = __float2bfloat16_rn(a), h1 = __float2bfloat16_rn(b);
    __nv_bfloat16 l0 = __float2bfloat16_rn(a - __bfloat162float(h0));
    __nv_bfloat16 l1 = __float2bfloat16_rn(b - __bfloat162float(h1));
    uh = (uint32_t)__bfloat16_as_ushort(h0) | ((uint32_t)__bfloat16_as_ushort(h1) << 16);
    ul = (uint32_t)__bfloat16_as_ushort(l0) | ((uint32_t)__bfloat16_as_ushort(l1) << 16);
}

// ---------------- prep kernels -------------------------------------------------------
__global__ void __launch_bounds__(256) k_init(const float* __restrict__ h0in,
                                              const float* __restrict__ bi,
                                              const float* __restrict__ bh)
{
    int idx = blockIdx.x * 256 + threadIdx.x;
    if (idx == 0) { g_arrive = 0u; g_gen = 0u; }
    if (idx < 64) g_flag[idx] = 0u;
    if (idx < 2 * Hv) g_bsum[idx] = bi[idx] + bh[idx];
    int j = idx & (Hv - 1);
    float v0 = h0in[j], v1 = h0in[Hv + j];
    __nv_bfloat16 h = __float2bfloat16_rn(v0);
    __nv_bfloat16 l = __float2bfloat16_rn(v0 - __bfloat162float(h));
    g_h0h[0][idx] = h; g_h0l[0][idx] = l; g_h0h[1][idx] = h; g_h0l[1][idx] = l;
    h = __float2bfloat16_rn(v1);
    l = __float2bfloat16_rn(v1 - __bfloat162float(h));
    g_h1h[0][idx] = h; g_h1l[0][idx] = l; g_h1h[1][idx] = h; g_h1l[1][idx] = l;
}

__global__ void __launch_bounds__(256) k_splitx(const float* __restrict__ x)
{
    size_t i = (size_t)blockIdx.x * 256 + threadIdx.x;
    float4 v = ((const float4*)x)[i];
    uint2 uh, ul;
    split4(v, uh, ul);
    ((uint2*)g_xh)[i] = uh;
    ((uint2*)g_xl)[i] = ul;
}

__global__ void k_splitw(const float* __restrict__ Wi, const float* __restrict__ Wh)
{
    __shared__ float t[32][33];
    int m = blockIdx.z;
    const float* W = (m == 0) ? Wh
                   : (m == 1) ? (Wi + (size_t)Hv * Hv)
                   : (m == 2) ? (Wh + (size_t)Hv * Hv) : Wi;
    int k0 = blockIdx.y * 32, n0 = blockIdx.x * 32;
    for (int r = threadIdx.y; r < 32; r += 8)
        t[r][threadIdx.x] = W[(size_t)(k0 + r) * Hv + n0 + threadIdx.x];
    __syncthreads();
    for (int r = threadIdx.y; r < 32; r += 8) {
        float v = t[threadIdx.x][r];
        __nv_bfloat16 h = __float2bfloat16_rn(v);
        __nv_bfloat16 l = __float2bfloat16_rn(v - __bfloat162float(h));
        size_t o = (size_t)(n0 + r) * Hv + k0 + threadIdx.x;
        g_Wth[m][o] = h;
        g_Wtl[m][o] = l;
    }
}

// ---------------- persistent wavefront kernel -----------------------------------------
// 128 CTAs: blockIdx = ctc*2 + rh.  ctc: seg = ctc>>4 (0:h0@Wh0 1:h0@Wi1 2:h1@Wh1 3:x@Wi0),
// ctn = ctc&15 (64-col tile).  rh: 64-row half.
// Pairs: (seg3 -> seg0) produce/consume pre-h0; (seg1 -> seg2) produce/consume pre-h1.
// One grid barrier per wave.
__global__ void __launch_bounds__(NTHR)
k_persist(float* __restrict__ out, int has_hn)
{
    extern __shared__ char smem[];
    const uint32_t sb = smem_u32(smem);
    const int tid  = threadIdx.x;
    const int lane = tid & 31;
    const int wid  = tid >> 5;
    const int ctc  = blockIdx.x >> 1;
    const int rh   = blockIdx.x & 1;
    const int r0   = rh * 64;
    const int seg  = ctc >> 4;
    const int ctn  = ctc & 15;
    const int nloc = ctn * 64;

    const int tw = wid & 3, khalf = wid >> 2;
    const int wr = tw & 1, wc = tw >> 1;

    const int pairIdx = ((seg == 1 || seg == 2) ? 32 : 0) + rh * 16 + ctn;
    const bool isProducer = (seg == 3) || (seg == 1);

    // A fragment addressing
    const int mA    = wr * 32 + ((lane >> 3) & 1) * 8 + (lane & 7);
    const uint32_t xorA   = (uint32_t)((mA & 7) * 16);
    const uint32_t abase0 = (uint32_t)(mA * 128);
    const uint32_t abase1 = (uint32_t)((mA + 16) * 128);

    // W fragment addressing
    const int nW    = wc * 32 + ((lane >> 4) & 1) * 8 + (lane & 7);
    const uint32_t xorW   = (uint32_t)((nW & 7) * 16);
    const uint32_t wbase0 = (uint32_t)(nW * 128);
    const uint32_t wbase1 = wbase0 + 16 * 128;

    const __nv_bfloat16* Whb = g_Wth[seg] + (size_t)nloc * Hv;
    const __nv_bfloat16* Wlb = g_Wtl[seg] + (size_t)nloc * Hv;

    auto load_tile = [&](uint32_t dst, const __nv_bfloat16* src, size_t rs) {
#pragma unroll
        for (int r = 0; r < 2; r++) {
            int i = tid + r * 256;
            int row = i >> 3, kg = i & 7;
            cp16(dst + swz(row * 128 + kg * 16), src + (size_t)row * rs + kg * 8);
        }
    };

    // ---- resident Wh slice (once) ----
    for (int c = 0; c < 16; c++)
        load_tile(sb + OFF_WRES + c * 8192, Whb + c * 64, Hv);
    asm volatile("cp.async.commit_group;" ::: "memory");
    asm volatile("cp.async.wait_group 0;" ::: "memory");
    __syncthreads();

    unsigned expect = 0;

    for (int w = 0; w <= Tv; w++) {
        const int p = w & 1;
        const bool active = (seg == 1) || (seg == 2) || (w < Tv);

        if (active) {
            const __nv_bfloat16 *Ah, *Al;
            size_t astr;
            if (seg <= 1)      { Ah = g_h0h[p] + (size_t)r0 * Hv; Al = g_h0l[p] + (size_t)r0 * Hv; astr = Hv; }
            else if (seg == 2) { Ah = g_h1h[p] + (size_t)r0 * Hv; Al = g_h1l[p] + (size_t)r0 * Hv; astr = Hv; }
            else { Ah = g_xh + ((size_t)r0 * Tv + w) * Hv; Al = g_xl + ((size_t)r0 * Tv + w) * Hv; astr = (size_t)Tv * Hv; }

            auto load_chunk = [&](int b, int c) {
                load_tile(sb + OFF_AH(b), Ah + c * 64, astr);
                load_tile(sb + OFF_AL(b), Al + c * 64, astr);
                load_tile(sb + OFF_WL(b), Wlb + c * 64, Hv);
                asm volatile("cp.async.commit_group;" ::: "memory");
            };

            float acc[8][4];
#pragma unroll
            for (int i = 0; i < 8; i++)
#pragma unroll
                for (int q = 0; q < 4; q++) acc[i][q] = 0.f;

            load_chunk(0, 0);
            load_chunk(1, 1);

#pragma unroll 1
            for (int c = 0; c < 16; c++) {
                const int b = c & 1;
                if (c < 15) asm volatile("cp.async.wait_group 1;" ::: "memory");
                else        asm volatile("cp.async.wait_group 0;" ::: "memory");
                __syncthreads();

                const uint32_t sWr = sb + OFF_WRES + c * 8192;
                uint32_t ah0[4], ah1[4], al0[4], al1[4], wh[8], wl[8];
#pragma unroll
                for (int kq = 0; kq < 2; kq++) {
                    const int kk = khalf * 2 + kq;
                    uint32_t ka = ((uint32_t)(kk * 32 + ((lane >> 4) & 1) * 16)) ^ xorA;
                    uint32_t kw = ((uint32_t)(kk * 32 + ((lane >> 3) & 1) * 16)) ^ xorW;
                    ldm4(ah0, sb + OFF_AH(b) + abase0 + ka);
                    ldm4(ah1, sb + OFF_AH(b) + abase1 + ka);
                    ldm4(al0, sb + OFF_AL(b) + abase0 + ka);
                    ldm4(al1, sb + OFF_AL(b) + abase1 + ka);
                    ldm4(wh,     sWr + wbase0 + kw);
                    ldm4(wh + 4, sWr + wbase1 + kw);
                    ldm4(wl,     sb + OFF_WL(b) + wbase0 + kw);
                    ldm4(wl + 4, sb + OFF_WL(b) + wbase1 + kw);
#pragma unroll
                    for (int i = 0; i < 2; i++) {
                        const uint32_t* ah = i ? ah1 : ah0;
                        const uint32_t* al = i ? al1 : al0;
#pragma unroll
                        for (int j = 0; j < 4; j++) {
                            const uint32_t* bh = &wh[(j >> 1) * 4 + (j & 1) * 2];
                            const uint32_t* bl = &wl[(j >> 1) * 4 + (j & 1) * 2];
                            float* a_ = acc[i * 4 + j];
                            mma16816(a_, ah, bh);
                            mma16816(a_, al, bh);
                            mma16816(a_, ah, bl);
                        }
                    }
                }
                __syncthreads();
                if (c + 2 < 16) load_chunk(b, c + 2);
            }

            // ---- combine khalves via smem ----
            float* cmb = (float*)(smem + OFF_CMB + tw * 4096);
            if (khalf) {
#pragma unroll
                for (int r = 0; r < 32; r++)
                    cmb[r * 32 + lane] = acc[r >> 2][r & 3];
            }
            __syncthreads();

            if (isProducer) {
                // ---- producer: write partial tile, release flag ----
                if (!khalf) {
                    float* part = g_P + (size_t)pairIdx * 4096;
                    const int g = lane >> 2, tq = lane & 3;
#pragma unroll
                    for (int i = 0; i < 2; i++) {
#pragma unroll
                        for (int j = 0; j < 4; j++) {
                            int t = i * 4 + j;
                            int rl = wr * 32 + i * 16 + g;
                            int cl = wc * 32 + j * 8 + tq * 2;
                            float2 v0, v1;
                            v0.x = acc[t][0] + cmb[(t * 4 + 0) * 32 + lane];
                            v0.y = acc[t][1] + cmb[(t * 4 + 1) * 32 + lane];
                            v1.x = acc[t][2] + cmb[(t * 4 + 2) * 32 + lane];
                            v1.y = acc[t][3] + cmb[(t * 4 + 3) * 32 + lane];
                            *(float2*)(part + rl * 64 + cl) = v0;
                            *(float2*)(part + (rl + 8) * 64 + cl) = v1;
                        }
                    }
                }
                __syncthreads();
                if (tid == 0) {
                    __threadfence();
                    atomicAdd(&g_flag[pairIdx], 1u);
                }
            } else {
                // ---- consumer: wait partner, fuse epilogue ----
                const bool consume = (seg == 0) ? true : (w >= 1);
                if (consume) {
                    if (tid == 0) {
                        while (*(volatile unsigned*)&g_flag[pairIdx] < (unsigned)(w + 1)) {}
                        __threadfence();
                    }
                    __syncthreads();
                    if (!khalf) {
                        const float* part = g_P + (size_t)pairIdx * 4096;
                        const int g = lane >> 2, tq = lane & 3;
                        __nv_bfloat16* Hh = (seg == 0) ? g_h0h[p ^ 1] : g_h1h[p ^ 1];
                        __nv_bfloat16* Hl = (seg == 0) ? g_h0l[p ^ 1] : g_h1l[p ^ 1];
                        const int bbase = (seg == 0) ? 0 : Hv;
#pragma unroll
                        for (int i = 0; i < 2; i++) {
#pragma unroll
                            for (int j = 0; j < 4; j++) {
                                int t = i * 4 + j;
                                int rl = wr * 32 + i * 16 + g;
                                int cl = wc * 32 + j * 8 + tq * 2;
                                int col = nloc + cl;
                                float2 bs = *(const float2*)&g_bsum[bbase + col];
                                float2 pa = __ldcg((const float2*)(part + rl * 64 + cl));
                                float2 pb = __ldcg((const float2*)(part + (rl + 8) * 64 + cl));
                                float s0 = acc[t][0] + cmb[(t * 4 + 0) * 32 + lane];
                                float s1 = acc[t][1] + cmb[(t * 4 + 1) * 32 + lane];
                                float s2 = acc[t][2] + cmb[(t * 4 + 2) * 32 + lane];
                                float s3 = acc[t][3] + cmb[(t * 4 + 3) * 32 + lane];
                                float z0 = tanhf(s0 + pa.x + bs.x);
                                float z1 = tanhf(s1 + pa.y + bs.y);
                                float z2 = tanhf(s2 + pb.x + bs.x);
                                float z3 = tanhf(s3 + pb.y + bs.y);
                                int b0r = r0 + rl, b1r = r0 + rl + 8;
                                uint32_t uh, ul;
                                split2(z0, z1, uh, ul);
                                *(uint32_t*)&Hh[b0r * Hv + col] = uh;
                                *(uint32_t*)&Hl[b0r * Hv + col] = ul;
                                split2(z2, z3, uh, ul);
                                *(uint32_t*)&Hh[b1r * Hv + col] = uh;
                                *(uint32_t*)&Hl[b1r * Hv + col] = ul;
                                if (seg == 2) {
                                    float2 o0; o0.x = z0; o0.y = z1;
                                    float2 o1; o1.x = z2; o1.y = z3;
                                    *(float2*)&out[((size_t)b0r * Tv + (w - 1)) * Hv + col] = o0;
                                    *(float2*)&out[((size_t)b1r * Tv + (w - 1)) * Hv + col] = o1;
                                    if (w == Tv && has_hn) {
                                        *(float2*)&out[(size_t)Bv * Tv * Hv + (size_t)b0r * 2 * Hv + Hv + col] = o0;
                                        *(float2*)&out[(size_t)Bv * Tv * Hv + (size_t)b1r * 2 * Hv + Hv + col] = o1;
                                    }
                                } else if (w == Tv - 1 && has_hn) {
                                    float2 o0; o0.x = z0; o0.y = z1;
                                    float2 o1; o1.x = z2; o1.y = z3;
                                    *(float2*)&out[(size_t)Bv * Tv * Hv + (size_t)b0r * 2 * Hv + col] = o0;
                                    *(float2*)&out[(size_t)Bv * Tv * Hv + (size_t)b1r * 2 * Hv + col] = o1;
                                }
                            }
                        }
                    }
                }
            }
        }
        gbar(++expect);
    }
}

// ---------------- launcher -----------------------------------------------------------
extern "C" void kernel_launch(void* const* d_in, const int* in_sizes, int n_in,
                              void* d_out, int out_size)
{
    (void)in_sizes; (void)n_in;
    const float* x  = (const float*)d_in[0];
    const float* h0 = (const float*)d_in[1];
    const float* Wi = (const float*)d_in[2];
    const float* bi = (const float*)d_in[3];
    const float* Wh = (const float*)d_in[4];
    const float* bh = (const float*)d_in[5];
    float* out = (float*)d_out;

    cudaFuncSetAttribute(k_persist, cudaFuncAttributeMaxDynamicSharedMemorySize, SMEM_SZ);

    int has_hn = (out_size >= Bv * Tv * Hv + Bv * 2 * Hv) ? 1 : 0;

    k_init<<<512, 256>>>(h0, bi, bh);
    k_splitx<<<32768, 256>>>(x);
    k_splitw<<<dim3(32, 32, 4), dim3(32, 8)>>>(Wi, Wh);
    k_persist<<<GRID, NTHR, SMEM_SZ>>>(out, has_hn);
}

// round 11
// speedup vs baseline: 1.1949x; 1.1949x over previous
#include <cuda_runtime.h>
#include <cuda_bf16.h>
#include <math.h>
#include <stdint.h>

#define Bv 128
#define Tv 256
#define Hv 1024
#define GRID 256
#define NTHR 256

// ---------------- scratch -----------------------------------------------------
__device__ __nv_bfloat16 g_xh[(size_t)Bv * Tv * Hv];
__device__ __nv_bfloat16 g_xl[(size_t)Bv * Tv * Hv];
__device__ __nv_bfloat16 g_Wth[4][(size_t)Hv * Hv];   // [n][k] hi: 0:Wh0 1:Wi1 2:Wh1 3:Wi0
__device__ __nv_bfloat16 g_Wtl[4][(size_t)Hv * Hv];   // [n][k] lo
__device__ __nv_bfloat16 g_h0h[2][Bv * Hv], g_h0l[2][Bv * Hv];
__device__ __nv_bfloat16 g_h1h[2][Bv * Hv], g_h1l[2][Bv * Hv];
__device__ float g_bsum[2 * Hv];
__device__ float g_C2[2][(size_t)Bv * 4096];          // K-half partial results
__device__ unsigned g_arrive, g_gen;

// ---------------- smem layout (dynamic, 112 KB -> 2 CTAs/SM) ---------------------
// [0, 64K)    resident Wh slice for this CTA's K-half: 8 chunk-tiles x 8KB
// [64K, ..)   double-buffered stream chunks: Ah | Al | Wl (8KB each)
#define OFF_WRES  0
#define OFF_AH(b) (65536 + (b) * 24576)
#define OFF_AL(b) (65536 + (b) * 24576 + 8192)
#define OFF_WL(b) (65536 + (b) * 24576 + 16384)
#define OFF_CMB   65536
#define SMEM_SZ   114688

// ---------------- PTX helpers ---------------------------------------------------
__device__ __forceinline__ uint32_t smem_u32(const void* p) {
    uint32_t a;
    asm("{ .reg .u64 t; cvta.to.shared.u64 t, %1; cvt.u32.u64 %0, t; }" : "=r"(a) : "l"(p));
    return a;
}
__device__ __forceinline__ uint32_t swz(uint32_t o) { return o ^ ((o >> 3) & 0x70); }
__device__ __forceinline__ void cp16(uint32_t s, const void* g) {
    asm volatile("cp.async.cg.shared.global [%0], [%1], 16;" :: "r"(s), "l"(g));
}
__device__ __forceinline__ void ldm4(uint32_t* r, uint32_t addr) {
    asm volatile("ldmatrix.sync.aligned.m8n8.x4.shared.b16 {%0,%1,%2,%3}, [%4];"
        : "=r"(r[0]), "=r"(r[1]), "=r"(r[2]), "=r"(r[3]) : "r"(addr));
}
__device__ __forceinline__ void mma16816(float* c, const uint32_t* a, const uint32_t* b) {
    asm volatile("mma.sync.aligned.m16n8k16.row.col.f32.bf16.bf16.f32 "
        "{%0,%1,%2,%3}, {%4,%5,%6,%7}, {%8,%9}, {%0,%1,%2,%3};"
        : "+f"(c[0]), "+f"(c[1]), "+f"(c[2]), "+f"(c[3])
        : "r"(a[0]), "r"(a[1]), "r"(a[2]), "r"(a[3]), "r"(b[0]), "r"(b[1]));
}

// ---------------- grid barrier ----------------------------------------------------
__device__ __forceinline__ void gbar(unsigned expect) {
    __threadfence();
    __syncthreads();
    if (threadIdx.x == 0) {
        unsigned a = atomicAdd(&g_arrive, 1u);
        if (a == GRID - 1) {
            atomicExch(&g_arrive, 0u);
            __threadfence();
            atomicAdd(&g_gen, 1u);
        } else {
            while (*(volatile unsigned*)&g_gen < expect) { __nanosleep(64); }
        }
        __threadfence();
    }
    __syncthreads();
}

// ---------------- bf16 split helpers ------------------------------------------------
__device__ __forceinline__ void split4(float4 v, uint2& uh, uint2& ul) {
    __nv_bfloat16 h0 = __float2bfloat16_rn(v.x), h1 = __float2bfloat16_rn(v.y);
    __nv_bfloat16 h2 = __float2bfloat16_rn(v.z), h3 = __float2bfloat16_rn(v.w);
    __nv_bfloat16 l0 = __float2bfloat16_rn(v.x - __bfloat162float(h0));
    __nv_bfloat16 l1 = __float2bfloat16_rn(v.y - __bfloat162float(h1));
    __nv_bfloat16 l2 = __float2bfloat16_rn(v.z - __bfloat162float(h2));
    __nv_bfloat16 l3 = __float2bfloat16_rn(v.w - __bfloat162float(h3));
    uh.x = (uint32_t)__bfloat16_as_ushort(h0) | ((uint32_t)__bfloat16_as_ushort(h1) << 16);
    uh.y = (uint32_t)__bfloat16_as_ushort(h2) | ((uint32_t)__bfloat16_as_ushort(h3) << 16);
    ul.x = (uint32_t)__bfloat16_as_ushort(l0) | ((uint32_t)__bfloat16_as_ushort(l1) << 16);
    ul.y = (uint32_t)__bfloat16_as_ushort(l2) | ((uint32_t)__bfloat16_as_ushort(l3) << 16);
}
__device__ __forceinline__ void split2(float a, float b, uint32_t& uh, uint32_t& ul) {
    __nv_bfloat16 h0 = __float2bfloat16_rn(a), h1 = __float2bfloat16_rn(b);
    __nv_bfloat16 l0 = __float2bfloat16_rn(a - __bfloat162float(h0));
    __nv_bfloat16 l1 = __float2bfloat16_rn(b - __bfloat162float(h1));
    uh = (uint32_t)__bfloat16_as_ushort(h0) | ((uint32_t)__bfloat16_as_ushort(h1) << 16);
    ul = (uint32_t)__bfloat16_as_ushort(l0) | ((uint32_t)__bfloat16_as_ushort(l1) << 16);
}

// ---------------- prep kernels -------------------------------------------------------
__global__ void __launch_bounds__(256) k_init(const float* __restrict__ h0in,
                                              const float* __restrict__ bi,
                                              const float* __restrict__ bh)
{
    int idx = blockIdx.x * 256 + threadIdx.x;
    if (idx == 0) { g_arrive = 0u; g_gen = 0u; }
    if (idx < 2 * Hv) g_bsum[idx] = bi[idx] + bh[idx];
    int j = idx & (Hv - 1);
    float v0 = h0in[j], v1 = h0in[Hv + j];
    __nv_bfloat16 h = __float2bfloat16_rn(v0);
    __nv_bfloat16 l = __float2bfloat16_rn(v0 - __bfloat162float(h));
    g_h0h[0][idx] = h; g_h0l[0][idx] = l; g_h0h[1][idx] = h; g_h0l[1][idx] = l;
    h = __float2bfloat16_rn(v1);
    l = __float2bfloat16_rn(v1 - __bfloat162float(h));
    g_h1h[0][idx] = h; g_h1l[0][idx] = l; g_h1h[1][idx] = h; g_h1l[1][idx] = l;
}

__global__ void __launch_bounds__(256) k_splitx(const float* __restrict__ x)
{
    size_t i = (size_t)blockIdx.x * 256 + threadIdx.x;
    float4 v = ((const float4*)x)[i];
    uint2 uh, ul;
    split4(v, uh, ul);
    ((uint2*)g_xh)[i] = uh;
    ((uint2*)g_xl)[i] = ul;
}

__global__ void k_splitw(const float* __restrict__ Wi, const float* __restrict__ Wh)
{
    __shared__ float t[32][33];
    int m = blockIdx.z;
    const float* W = (m == 0) ? Wh
                   : (m == 1) ? (Wi + (size_t)Hv * Hv)
                   : (m == 2) ? (Wh + (size_t)Hv * Hv) : Wi;
    int k0 = blockIdx.y * 32, n0 = blockIdx.x * 32;
    for (int r = threadIdx.y; r < 32; r += 8)
        t[r][threadIdx.x] = W[(size_t)(k0 + r) * Hv + n0 + threadIdx.x];
    __syncthreads();
    for (int r = threadIdx.y; r < 32; r += 8) {
        float v = t[threadIdx.x][r];
        __nv_bfloat16 h = __float2bfloat16_rn(v);
        __nv_bfloat16 l = __float2bfloat16_rn(v - __bfloat162float(h));
        size_t o = (size_t)(n0 + r) * Hv + k0 + threadIdx.x;
        g_Wth[m][o] = h;
        g_Wtl[m][o] = l;
    }
}

// ---------------- persistent wavefront kernel -----------------------------------------
// 256 CTAs: blockIdx = ctc*4 + rh*2 + ks.
//   ctc (0..63): seg = ctc>>4 (0:h0@Wh0 1:h0@Wi1 2:h1@Wh1 3:x@Wi0), ctn = ctc&15.
//   rh: 64-row half.  ks: K-half (8 chunks of 64).
// Each CTA computes C[64x64] over its K-half into g_C2[ks]; finalize sums both.
// 2 CTAs resident per SM -> cross-CTA latency overlap.
__global__ void __launch_bounds__(NTHR, 2)
k_persist(float* __restrict__ out, int has_hn)
{
    extern __shared__ char smem[];
    const uint32_t sb = smem_u32(smem);
    const int tid  = threadIdx.x;
    const int lane = tid & 31;
    const int wid  = tid >> 5;
    const int ks   = blockIdx.x & 1;
    const int rh   = (blockIdx.x >> 1) & 1;
    const int ctc  = blockIdx.x >> 2;
    const int r0   = rh * 64;
    const int seg  = ctc >> 4;
    const int nloc = (ctc & 15) * 64;
    const int kbase = ks * 8;              // chunk offset of this K-half

    const int tw = wid & 3, khalf = wid >> 2;
    const int wr = tw & 1, wc = tw >> 1;

    // A fragment addressing (two m16 tiles at rows wr*32, wr*32+16)
    const int mA    = wr * 32 + ((lane >> 3) & 1) * 8 + (lane & 7);
    const uint32_t xorA   = (uint32_t)((mA & 7) * 16);
    const uint32_t abase0 = (uint32_t)(mA * 128);
    const uint32_t abase1 = (uint32_t)((mA + 16) * 128);

    // W fragment addressing (two n16 groups)
    const int nW    = wc * 32 + ((lane >> 4) & 1) * 8 + (lane & 7);
    const uint32_t xorW   = (uint32_t)((nW & 7) * 16);
    const uint32_t wbase0 = (uint32_t)(nW * 128);
    const uint32_t wbase1 = wbase0 + 16 * 128;

    const __nv_bfloat16* Whb = g_Wth[seg] + (size_t)nloc * Hv;
    const __nv_bfloat16* Wlb = g_Wtl[seg] + (size_t)nloc * Hv;

    auto load_tile = [&](uint32_t dst, const __nv_bfloat16* src, size_t rs) {
#pragma unroll
        for (int r = 0; r < 2; r++) {
            int i = tid + r * 256;
            int row = i >> 3, kg = i & 7;
            cp16(dst + swz(row * 128 + kg * 16), src + (size_t)row * rs + kg * 8);
        }
    };

    // ---- resident Wh slice for this K-half (once) ----
    for (int c = 0; c < 8; c++)
        load_tile(sb + OFF_WRES + c * 8192, Whb + (kbase + c) * 64, Hv);
    asm volatile("cp.async.commit_group;" ::: "memory");
    asm volatile("cp.async.wait_group 0;" ::: "memory");
    __syncthreads();

    unsigned expect = 0;
    const int gid = blockIdx.x * NTHR + tid;   // 0..65535 == Bv*Hv/2

    for (int w = 0; w <= Tv; w++) {
        const int p = w & 1;
        const bool active = (seg == 1) || (seg == 2) || (w < Tv);

        if (active) {
            const __nv_bfloat16 *Ah, *Al;
            size_t astr;
            if (seg <= 1)      { Ah = g_h0h[p] + (size_t)r0 * Hv; Al = g_h0l[p] + (size_t)r0 * Hv; astr = Hv; }
            else if (seg == 2) { Ah = g_h1h[p] + (size_t)r0 * Hv; Al = g_h1l[p] + (size_t)r0 * Hv; astr = Hv; }
            else { Ah = g_xh + ((size_t)r0 * Tv + w) * Hv; Al = g_xl + ((size_t)r0 * Tv + w) * Hv; astr = (size_t)Tv * Hv; }

            auto load_chunk = [&](int b, int c) {
                load_tile(sb + OFF_AH(b), Ah + (kbase + c) * 64, astr);
                load_tile(sb + OFF_AL(b), Al + (kbase + c) * 64, astr);
                load_tile(sb + OFF_WL(b), Wlb + (kbase + c) * 64, Hv);
                asm volatile("cp.async.commit_group;" ::: "memory");
            };

            float acc[8][4];
#pragma unroll
            for (int i = 0; i < 8; i++)
#pragma unroll
                for (int q = 0; q < 4; q++) acc[i][q] = 0.f;

            load_chunk(0, 0);
            load_chunk(1, 1);

#pragma unroll 1
            for (int c = 0; c < 8; c++) {
                const int b = c & 1;
                if (c < 7) asm volatile("cp.async.wait_group 1;" ::: "memory");
                else       asm volatile("cp.async.wait_group 0;" ::: "memory");
                __syncthreads();

                const uint32_t sWr = sb + OFF_WRES + c * 8192;
                uint32_t ah0[4], ah1[4], al0[4], al1[4], wh[8], wl[8];
#pragma unroll
                for (int kq = 0; kq < 2; kq++) {
                    const int kk = khalf * 2 + kq;
                    uint32_t ka = ((uint32_t)(kk * 32 + ((lane >> 4) & 1) * 16)) ^ xorA;
                    uint32_t kw = ((uint32_t)(kk * 32 + ((lane >> 3) & 1) * 16)) ^ xorW;
                    ldm4(ah0, sb + OFF_AH(b) + abase0 + ka);
                    ldm4(ah1, sb + OFF_AH(b) + abase1 + ka);
                    ldm4(al0, sb + OFF_AL(b) + abase0 + ka);
                    ldm4(al1, sb + OFF_AL(b) + abase1 + ka);
                    ldm4(wh,     sWr + wbase0 + kw);
                    ldm4(wh + 4, sWr + wbase1 + kw);
                    ldm4(wl,     sb + OFF_WL(b) + wbase0 + kw);
                    ldm4(wl + 4, sb + OFF_WL(b) + wbase1 + kw);
#pragma unroll
                    for (int i = 0; i < 2; i++) {
                        const uint32_t* ah = i ? ah1 : ah0;
                        const uint32_t* al = i ? al1 : al0;
#pragma unroll
                        for (int j = 0; j < 4; j++) {
                            const uint32_t* bh = &wh[(j >> 1) * 4 + (j & 1) * 2];
                            const uint32_t* bl = &wl[(j >> 1) * 4 + (j & 1) * 2];
                            float* a_ = acc[i * 4 + j];
                            mma16816(a_, ah, bh);
                            mma16816(a_, al, bh);
                            mma16816(a_, ah, bl);
                        }
                    }
                }
                __syncthreads();
                if (c + 2 < 8) load_chunk(b, c + 2);
            }

            // ---- combine khalves via smem; khalf0 warps write C tile ----
            float* cmb = (float*)(smem + OFF_CMB + tw * 4096);
            if (khalf) {
#pragma unroll
                for (int r = 0; r < 32; r++)
                    cmb[r * 32 + lane] = acc[r >> 2][r & 3];
            }
            __syncthreads();
            if (!khalf) {
#pragma unroll
                for (int r = 0; r < 32; r++)
                    acc[r >> 2][r & 3] += cmb[r * 32 + lane];
                float* Cg = g_C2[ks];
                const int g = lane >> 2, tq = lane & 3;
#pragma unroll
                for (int i = 0; i < 2; i++) {
                    float* Cb = Cg + (size_t)(r0 + wr * 32 + i * 16 + g) * 4096
                              + ctc * 64 + wc * 32 + tq * 2;
#pragma unroll
                    for (int j = 0; j < 4; j++) {
                        int t = i * 4 + j;
                        float2 v0, v1;
                        v0.x = acc[t][0]; v0.y = acc[t][1];
                        v1.x = acc[t][2]; v1.y = acc[t][3];
                        *(float2*)(Cb + j * 8) = v0;
                        *(float2*)(Cb + 8 * 4096 + j * 8) = v1;
                    }
                }
            }
        }
        gbar(++expect);

        // ---------------- finalize: one float2 per thread ----------------
        {
            int bb = gid >> 9;
            int jj = (gid & 511) << 1;
            const float* Cr0 = g_C2[0] + (size_t)bb * 4096 + jj;
            const float* Cr1 = g_C2[1] + (size_t)bb * 4096 + jj;

            if (w < Tv) {
                float2 a0 = __ldcg((const float2*)(Cr0));
                float2 a3 = __ldcg((const float2*)(Cr0 + 3072));
                float2 b0 = __ldcg((const float2*)(Cr1));
                float2 b3 = __ldcg((const float2*)(Cr1 + 3072));
                float2 bs = *(const float2*)&g_bsum[jj];
                float z0 = tanhf(a0.x + b0.x + a3.x + b3.x + bs.x);
                float z1 = tanhf(a0.y + b0.y + a3.y + b3.y + bs.y);
                uint32_t uh, ul;
                split2(z0, z1, uh, ul);
                *(uint32_t*)&g_h0h[p ^ 1][bb * Hv + jj] = uh;
                *(uint32_t*)&g_h0l[p ^ 1][bb * Hv + jj] = ul;
                if (w == Tv - 1 && has_hn) {
                    float2 o; o.x = z0; o.y = z1;
                    *(float2*)&out[(size_t)Bv * Tv * Hv + (size_t)bb * 2 * Hv + jj] = o;
                }
            }
            if (w >= 1) {
                float2 a1 = __ldcg((const float2*)(Cr0 + 1024));
                float2 a2 = __ldcg((const float2*)(Cr0 + 2048));
                float2 b1 = __ldcg((const float2*)(Cr1 + 1024));
                float2 b2 = __ldcg((const float2*)(Cr1 + 2048));
                float2 bs = *(const float2*)&g_bsum[Hv + jj];
                float z0 = tanhf(a1.x + b1.x + a2.x + b2.x + bs.x);
                float z1 = tanhf(a1.y + b1.y + a2.y + b2.y + bs.y);
                uint32_t uh, ul;
                split2(z0, z1, uh, ul);
                *(uint32_t*)&g_h1h[p ^ 1][bb * Hv + jj] = uh;
                *(uint32_t*)&g_h1l[p ^ 1][bb * Hv + jj] = ul;
                float2 o; o.x = z0; o.y = z1;
                *(float2*)&out[((size_t)bb * Tv + (w - 1)) * Hv + jj] = o;
                if (w == Tv && has_hn)
                    *(float2*)&out[(size_t)Bv * Tv * Hv + (size_t)bb * 2 * Hv + Hv + jj] = o;
            }
        }
        gbar(++expect);
    }
}

// ---------------- launcher -----------------------------------------------------------
extern "C" void kernel_launch(void* const* d_in, const int* in_sizes, int n_in,
                              void* d_out, int out_size)
{
    (void)in_sizes; (void)n_in;
    const float* x  = (const float*)d_in[0];
    const float* h0 = (const float*)d_in[1];
    const float* Wi = (const float*)d_in[2];
    const float* bi = (const float*)d_in[3];
    const float* Wh = (const float*)d_in[4];
    const float* bh = (const float*)d_in[5];
    float* out = (float*)d_out;

    cudaFuncSetAttribute(k_persist, cudaFuncAttributeMaxDynamicSharedMemorySize, SMEM_SZ);

    int has_hn = (out_size >= Bv * Tv * Hv + Bv * 2 * Hv) ? 1 : 0;

    k_init<<<512, 256>>>(h0, bi, bh);
    k_splitx<<<32768, 256>>>(x);
    k_splitw<<<dim3(32, 32, 4), dim3(32, 8)>>>(Wi, Wh);
    k_persist<<<GRID, NTHR, SMEM_SZ>>>(out, has_hn);
}

// round 12
// speedup vs baseline: 1.7586x; 1.4718x over previous
#include <cuda_runtime.h>
#include <cuda_fp16.h>
#include <math.h>
#include <stdint.h>

#define Bv 128
#define Tv 256
#define Hv 1024
#define GRID 256
#define NTHR 256

// ---------------- scratch -----------------------------------------------------
__device__ __half g_x16[(size_t)Bv * Tv * Hv];
__device__ __half g_Wt[4][(size_t)Hv * Hv];           // [n][k] fp16: 0:Wh0 1:Wi1 2:Wh1 3:Wi0
__device__ __half g_h0[2][Bv * Hv], g_h1[2][Bv * Hv]; // fp16 ping-pong states
__device__ float g_bsum[2 * Hv];
__device__ float g_C2[2][(size_t)Bv * 4096];          // K-half partial results
__device__ unsigned g_arrive, g_gen;

// ---------------- smem layout (dynamic, 80 KB -> 2 CTAs/SM) ----------------------
// [0, 64K)    resident W slice for this CTA's K-half: 8 chunk-tiles x 8KB
// [64K, 80K)  double-buffered A stream (8KB each); CMB (16KB) overlays A buffers
#define OFF_WRES  0
#define OFF_A(b)  (65536 + (b) * 8192)
#define OFF_CMB   65536
#define SMEM_SZ   81920

// ---------------- PTX helpers ---------------------------------------------------
__device__ __forceinline__ uint32_t smem_u32(const void* p) {
    uint32_t a;
    asm("{ .reg .u64 t; cvta.to.shared.u64 t, %1; cvt.u32.u64 %0, t; }" : "=r"(a) : "l"(p));
    return a;
}
__device__ __forceinline__ uint32_t swz(uint32_t o) { return o ^ ((o >> 3) & 0x70); }
__device__ __forceinline__ void cp16(uint32_t s, const void* g) {
    asm volatile("cp.async.cg.shared.global [%0], [%1], 16;" :: "r"(s), "l"(g));
}
__device__ __forceinline__ void ldm4(uint32_t* r, uint32_t addr) {
    asm volatile("ldmatrix.sync.aligned.m8n8.x4.shared.b16 {%0,%1,%2,%3}, [%4];"
        : "=r"(r[0]), "=r"(r[1]), "=r"(r[2]), "=r"(r[3]) : "r"(addr));
}
__device__ __forceinline__ void mma16816(float* c, const uint32_t* a, const uint32_t* b) {
    asm volatile("mma.sync.aligned.m16n8k16.row.col.f32.f16.f16.f32 "
        "{%0,%1,%2,%3}, {%4,%5,%6,%7}, {%8,%9}, {%0,%1,%2,%3};"
        : "+f"(c[0]), "+f"(c[1]), "+f"(c[2]), "+f"(c[3])
        : "r"(a[0]), "r"(a[1]), "r"(a[2]), "r"(a[3]), "r"(b[0]), "r"(b[1]));
}

// ---------------- grid barrier (busy-wait) ----------------------------------------
__device__ __forceinline__ void gbar(unsigned expect) {
    __threadfence();
    __syncthreads();
    if (threadIdx.x == 0) {
        unsigned a = atomicAdd(&g_arrive, 1u);
        if (a == GRID - 1) {
            atomicExch(&g_arrive, 0u);
            __threadfence();
            atomicAdd(&g_gen, 1u);
        } else {
            while (*(volatile unsigned*)&g_gen < expect) {}
        }
        __threadfence();
    }
    __syncthreads();
}

// ---------------- prep kernels -------------------------------------------------------
__global__ void __launch_bounds__(256) k_init(const float* __restrict__ h0in,
                                              const float* __restrict__ bi,
                                              const float* __restrict__ bh)
{
    int idx = blockIdx.x * 256 + threadIdx.x;   // 512 blocks = Bv*Hv
    if (idx == 0) { g_arrive = 0u; g_gen = 0u; }
    if (idx < 2 * Hv) g_bsum[idx] = bi[idx] + bh[idx];
    int j = idx & (Hv - 1);
    __half v0 = __float2half_rn(h0in[j]);
    __half v1 = __float2half_rn(h0in[Hv + j]);
    g_h0[0][idx] = v0; g_h0[1][idx] = v0;
    g_h1[0][idx] = v1; g_h1[1][idx] = v1;
}

__global__ void __launch_bounds__(256) k_cvtx(const float* __restrict__ x)
{
    size_t i = (size_t)blockIdx.x * 256 + threadIdx.x;   // 32768 blocks, float4 each
    float4 v = ((const float4*)x)[i];
    __half2 a = __floats2half2_rn(v.x, v.y);
    __half2 b = __floats2half2_rn(v.z, v.w);
    uint2 o;
    o.x = *(uint32_t*)&a;
    o.y = *(uint32_t*)&b;
    ((uint2*)g_x16)[i] = o;
}

__global__ void k_cvtw(const float* __restrict__ Wi, const float* __restrict__ Wh)
{
    __shared__ float t[32][33];
    int m = blockIdx.z;
    const float* W = (m == 0) ? Wh
                   : (m == 1) ? (Wi + (size_t)Hv * Hv)
                   : (m == 2) ? (Wh + (size_t)Hv * Hv) : Wi;
    int k0 = blockIdx.y * 32, n0 = blockIdx.x * 32;
    for (int r = threadIdx.y; r < 32; r += 8)
        t[r][threadIdx.x] = W[(size_t)(k0 + r) * Hv + n0 + threadIdx.x];
    __syncthreads();
    for (int r = threadIdx.y; r < 32; r += 8)
        g_Wt[m][(size_t)(n0 + r) * Hv + k0 + threadIdx.x] = __float2half_rn(t[threadIdx.x][r]);
}

// ---------------- persistent wavefront kernel -----------------------------------------
// 256 CTAs: blockIdx = ctc*4 + rh*2 + ks.
//   ctc: seg = ctc>>4 (0:h0@Wh0 1:h0@Wi1 2:h1@Wh1 3:x@Wi0), ctn = ctc&15 (64-col tile).
//   rh: 64-row half.  ks: K-half (8 chunks of 64).
// fp16 single-pass MMA; W resident in smem; A streamed per chunk.
__global__ void __launch_bounds__(NTHR, 2)
k_persist(float* __restrict__ out, int has_hn)
{
    extern __shared__ char smem[];
    const uint32_t sb = smem_u32(smem);
    const int tid  = threadIdx.x;
    const int lane = tid & 31;
    const int wid  = tid >> 5;
    const int ks   = blockIdx.x & 1;
    const int rh   = (blockIdx.x >> 1) & 1;
    const int ctc  = blockIdx.x >> 2;
    const int r0   = rh * 64;
    const int seg  = ctc >> 4;
    const int nloc = (ctc & 15) * 64;
    const int kbase = ks * 8;

    const int tw = wid & 3, khalf = wid >> 2;
    const int wr = tw & 1, wc = tw >> 1;

    // A fragment addressing (two m16 tiles at rows wr*32, wr*32+16)
    const int mA    = wr * 32 + ((lane >> 3) & 1) * 8 + (lane & 7);
    const uint32_t xorA   = (uint32_t)((mA & 7) * 16);
    const uint32_t abase0 = (uint32_t)(mA * 128);
    const uint32_t abase1 = (uint32_t)((mA + 16) * 128);

    // W fragment addressing (two n16 groups)
    const int nW    = wc * 32 + ((lane >> 4) & 1) * 8 + (lane & 7);
    const uint32_t xorW   = (uint32_t)((nW & 7) * 16);
    const uint32_t wbase0 = (uint32_t)(nW * 128);
    const uint32_t wbase1 = wbase0 + 16 * 128;

    const __half* Wb = g_Wt[seg] + (size_t)nloc * Hv;

    auto load_tile = [&](uint32_t dst, const __half* src, size_t rs) {
#pragma unroll
        for (int r = 0; r < 2; r++) {
            int i = tid + r * 256;
            int row = i >> 3, kg = i & 7;
            cp16(dst + swz(row * 128 + kg * 16), src + (size_t)row * rs + kg * 8);
        }
    };

    // ---- resident W slice for this K-half (once) ----
    for (int c = 0; c < 8; c++)
        load_tile(sb + OFF_WRES + c * 8192, Wb + (kbase + c) * 64, Hv);
    asm volatile("cp.async.commit_group;" ::: "memory");
    asm volatile("cp.async.wait_group 0;" ::: "memory");
    __syncthreads();

    unsigned expect = 0;
    const int gid = blockIdx.x * NTHR + tid;   // 0..65535 == Bv*Hv/2

    for (int w = 0; w <= Tv; w++) {
        const int p = w & 1;
        const bool active = (seg == 1) || (seg == 2) || (w < Tv);

        if (active) {
            const __half* A;
            size_t astr;
            if (seg <= 1)      { A = g_h0[p] + (size_t)r0 * Hv; astr = Hv; }
            else if (seg == 2) { A = g_h1[p] + (size_t)r0 * Hv; astr = Hv; }
            else { A = g_x16 + ((size_t)r0 * Tv + w) * Hv; astr = (size_t)Tv * Hv; }

            auto load_chunk = [&](int b, int c) {
                load_tile(sb + OFF_A(b), A + (kbase + c) * 64, astr);
                asm volatile("cp.async.commit_group;" ::: "memory");
            };

            float acc[8][4];
#pragma unroll
            for (int i = 0; i < 8; i++)
#pragma unroll
                for (int q = 0; q < 4; q++) acc[i][q] = 0.f;

            load_chunk(0, 0);
            load_chunk(1, 1);

#pragma unroll 1
            for (int c = 0; c < 8; c++) {
                const int b = c & 1;
                if (c < 7) asm volatile("cp.async.wait_group 1;" ::: "memory");
                else       asm volatile("cp.async.wait_group 0;" ::: "memory");
                __syncthreads();

                const uint32_t sWr = sb + OFF_WRES + c * 8192;
                uint32_t a0[4], a1[4], wf[8];
#pragma unroll
                for (int kq = 0; kq < 2; kq++) {
                    const int kk = khalf * 2 + kq;
                    uint32_t ka = ((uint32_t)(kk * 32 + ((lane >> 4) & 1) * 16)) ^ xorA;
                    uint32_t kw = ((uint32_t)(kk * 32 + ((lane >> 3) & 1) * 16)) ^ xorW;
                    ldm4(a0, sb + OFF_A(b) + abase0 + ka);
                    ldm4(a1, sb + OFF_A(b) + abase1 + ka);
                    ldm4(wf,     sWr + wbase0 + kw);
                    ldm4(wf + 4, sWr + wbase1 + kw);
#pragma unroll
                    for (int i = 0; i < 2; i++) {
                        const uint32_t* aa = i ? a1 : a0;
#pragma unroll
                        for (int j = 0; j < 4; j++)
                            mma16816(acc[i * 4 + j], aa, &wf[(j >> 1) * 4 + (j & 1) * 2]);
                    }
                }
                __syncthreads();
                if (c + 2 < 8) load_chunk(b, c + 2);
            }

            // ---- combine khalves via smem; khalf0 warps write C tile ----
            float* cmb = (float*)(smem + OFF_CMB + tw * 4096);
            if (khalf) {
#pragma unroll
                for (int r = 0; r < 32; r++)
                    cmb[r * 32 + lane] = acc[r >> 2][r & 3];
            }
            __syncthreads();
            if (!khalf) {
#pragma unroll
                for (int r = 0; r < 32; r++)
                    acc[r >> 2][r & 3] += cmb[r * 32 + lane];
                float* Cg = g_C2[ks];
                const int g = lane >> 2, tq = lane & 3;
#pragma unroll
                for (int i = 0; i < 2; i++) {
                    float* Cb = Cg + (size_t)(r0 + wr * 32 + i * 16 + g) * 4096
                              + ctc * 64 + wc * 32 + tq * 2;
#pragma unroll
                    for (int j = 0; j < 4; j++) {
                        int t = i * 4 + j;
                        float2 v0, v1;
                        v0.x = acc[t][0]; v0.y = acc[t][1];
                        v1.x = acc[t][2]; v1.y = acc[t][3];
                        *(float2*)(Cb + j * 8) = v0;
                        *(float2*)(Cb + 8 * 4096 + j * 8) = v1;
                    }
                }
            }
        }
        gbar(++expect);

        // ---------------- finalize: one float2 per thread ----------------
        {
            int bb = gid >> 9;
            int jj = (gid & 511) << 1;
            const float* Cr0 = g_C2[0] + (size_t)bb * 4096 + jj;
            const float* Cr1 = g_C2[1] + (size_t)bb * 4096 + jj;

            if (w < Tv) {
                float2 a0 = __ldcg((const float2*)(Cr0));
                float2 a3 = __ldcg((const float2*)(Cr0 + 3072));
                float2 b0 = __ldcg((const float2*)(Cr1));
                float2 b3 = __ldcg((const float2*)(Cr1 + 3072));
                float2 bs = *(const float2*)&g_bsum[jj];
                float z0 = tanhf(a0.x + b0.x + a3.x + b3.x + bs.x);
                float z1 = tanhf(a0.y + b0.y + a3.y + b3.y + bs.y);
                __half2 hz = __floats2half2_rn(z0, z1);
                *(uint32_t*)&g_h0[p ^ 1][bb * Hv + jj] = *(uint32_t*)&hz;
                if (w == Tv - 1 && has_hn) {
                    float2 o; o.x = z0; o.y = z1;
                    *(float2*)&out[(size_t)Bv * Tv * Hv + (size_t)bb * 2 * Hv + jj] = o;
                }
            }
            if (w >= 1) {
                float2 a1 = __ldcg((const float2*)(Cr0 + 1024));
                float2 a2 = __ldcg((const float2*)(Cr0 + 2048));
                float2 b1 = __ldcg((const float2*)(Cr1 + 1024));
                float2 b2 = __ldcg((const float2*)(Cr1 + 2048));
                float2 bs = *(const float2*)&g_bsum[Hv + jj];
                float z0 = tanhf(a1.x + b1.x + a2.x + b2.x + bs.x);
                float z1 = tanhf(a1.y + b1.y + a2.y + b2.y + bs.y);
                __half2 hz = __floats2half2_rn(z0, z1);
                *(uint32_t*)&g_h1[p ^ 1][bb * Hv + jj] = *(uint32_t*)&hz;
                float2 o; o.x = z0; o.y = z1;
                *(float2*)&out[((size_t)bb * Tv + (w - 1)) * Hv + jj] = o;
                if (w == Tv && has_hn)
                    *(float2*)&out[(size_t)Bv * Tv * Hv + (size_t)bb * 2 * Hv + Hv + jj] = o;
            }
        }
        gbar(++expect);
    }
}

// ---------------- launcher -----------------------------------------------------------
extern "C" void kernel_launch(void* const* d_in, const int* in_sizes, int n_in,
                              void* d_out, int out_size)
{
    (void)in_sizes; (void)n_in;
    const float* x  = (const float*)d_in[0];
    const float* h0 = (const float*)d_in[1];
    const float* Wi = (const float*)d_in[2];
    const float* bi = (const float*)d_in[3];
    const float* Wh = (const float*)d_in[4];
    const float* bh = (const float*)d_in[5];
    float* out = (float*)d_out;

    cudaFuncSetAttribute(k_persist, cudaFuncAttributeMaxDynamicSharedMemorySize, SMEM_SZ);

    int has_hn = (out_size >= Bv * Tv * Hv + Bv * 2 * Hv) ? 1 : 0;

    k_init<<<512, 256>>>(h0, bi, bh);
    k_cvtx<<<32768, 256>>>(x);
    k_cvtw<<<dim3(32, 32, 4), dim3(32, 8)>>>(Wi, Wh);
    k_persist<<<GRID, NTHR, SMEM_SZ>>>(out, has_hn);
}